// round 15
// baseline (speedup 1.0000x reference)
#include <cuda_runtime.h>
#include <cuda_fp16.h>

#define C_MLP 32
#define NV    10              // v = (x,y,z,f0..4,cx,cy)
#define NPAIR 55              // upper triangle of 10x10
#define NSTAT 65              // 55 + 10
#define GRID_A 296
#define BLK_A  256
#define NSLICE 15             // stageB reduction slices
#define PSIZE  0.075f
#define XMIN  -54.0f
#define YMIN  -54.0f
#define CZ    -1.0f
#define BN_EPS 1e-3f
#define MMAX   131072
#define CAP    24             // P(cnt>24) ~ 3e-8 for Poisson(6.67)

// static scratch (BSS zero-init; g_cnt kept zeroed by pool_kernel)
__device__ float g_part[GRID_A * 72];        // per-block partial stats
__device__ float g_A[NV * C_MLP];            // folded weights A' (10 x 32)
__device__ float g_e[C_MLP];                 // folded bias
__device__ int   g_cnt[MMAX];
__device__ uint4 g_pay[(size_t)MMAX * CAP];  // fp16 payloads (16B/pt): xc,yc,z,f0..f4

__device__ __forceinline__ unsigned pack_h2(float a, float b) {
    __half2 h = __floats2half2_rn(a, b);
    unsigned u;
    memcpy(&u, &h, 4);
    return u;
}

// ---------------------------------------------------------------------------
// Scatter: compute pillar-relative coords, pack 8 fp16, one STG.128.
// ---------------------------------------------------------------------------
__global__ __launch_bounds__(256)
void scatter_kernel(const float* __restrict__ xyz,
                    const float* __restrict__ ptf,
                    const int*   __restrict__ pil,
                    const int*   __restrict__ psi,
                    int N)
{
    int i = blockIdx.x * blockDim.x + threadIdx.x;
    if (i >= N) return;
    int p  = psi[i];
    int py = pil[3 * p + 1];
    int px = pil[3 * p + 2];
    float cx = ((float)px + 0.5f) * PSIZE + XMIN;
    float cy = ((float)py + 0.5f) * PSIZE + YMIN;
    float x  = xyz[3 * i + 0] - cx;
    float y  = xyz[3 * i + 1] - cy;
    float z  = xyz[3 * i + 2];
    float f0 = ptf[5 * i + 0];
    float f1 = ptf[5 * i + 1];
    float f2 = ptf[5 * i + 2];
    float f3 = ptf[5 * i + 3];
    float f4 = ptf[5 * i + 4];

    uint4 pk;
    pk.x = pack_h2(x,  y);
    pk.y = pack_h2(z,  f0);
    pk.z = pack_h2(f1, f2);
    pk.w = pack_h2(f3, f4);

    int pos = atomicAdd(&g_cnt[p], 1);
    if (pos < CAP) g_pay[(size_t)p * CAP + pos] = pk;
}

// ---------------------------------------------------------------------------
// Stats: sums + second moments of v = (x,y,z,f0..4,cx,cy). (fp32 exact)
// ---------------------------------------------------------------------------
__global__ __launch_bounds__(BLK_A)
void stats_kernel(const float* __restrict__ xyz,
                  const float* __restrict__ ptf,
                  const int*   __restrict__ pil,
                  const int*   __restrict__ psi,
                  int N)
{
    float acc[NPAIR];
    float s[NV];
#pragma unroll
    for (int j = 0; j < NPAIR; j++) acc[j] = 0.f;
#pragma unroll
    for (int j = 0; j < NV; j++) s[j] = 0.f;

    const int stride = GRID_A * BLK_A;
    for (int i = blockIdx.x * BLK_A + threadIdx.x; i < N; i += stride) {
        int p  = psi[i];
        int py = pil[3 * p + 1];
        int px = pil[3 * p + 2];
        float v[NV];
        v[0] = xyz[3 * i + 0];
        v[1] = xyz[3 * i + 1];
        v[2] = xyz[3 * i + 2];
#pragma unroll
        for (int k = 0; k < 5; k++) v[3 + k] = ptf[5 * i + k];
        v[8] = ((float)px + 0.5f) * PSIZE + XMIN;
        v[9] = ((float)py + 0.5f) * PSIZE + YMIN;

        int j = 0;
#pragma unroll
        for (int a = 0; a < NV; a++) {
            s[a] += v[a];
#pragma unroll
            for (int b = a; b < NV; b++) {
                acc[j] = fmaf(v[a], v[b], acc[j]);
                j++;
            }
        }
    }

#pragma unroll
    for (int j = 0; j < NPAIR; j++) {
        float t = acc[j];
        t += __shfl_xor_sync(0xffffffffu, t, 16);
        t += __shfl_xor_sync(0xffffffffu, t, 8);
        t += __shfl_xor_sync(0xffffffffu, t, 4);
        t += __shfl_xor_sync(0xffffffffu, t, 2);
        t += __shfl_xor_sync(0xffffffffu, t, 1);
        acc[j] = t;
    }
#pragma unroll
    for (int j = 0; j < NV; j++) {
        float t = s[j];
        t += __shfl_xor_sync(0xffffffffu, t, 16);
        t += __shfl_xor_sync(0xffffffffu, t, 8);
        t += __shfl_xor_sync(0xffffffffu, t, 4);
        t += __shfl_xor_sync(0xffffffffu, t, 2);
        t += __shfl_xor_sync(0xffffffffu, t, 1);
        s[j] = t;
    }

    __shared__ float sm[BLK_A / 32][NSTAT];
    int lane = threadIdx.x & 31;
    int wid  = threadIdx.x >> 5;
    if (lane == 0) {
#pragma unroll
        for (int j = 0; j < NPAIR; j++) sm[wid][j] = acc[j];
#pragma unroll
        for (int j = 0; j < NV; j++) sm[wid][NPAIR + j] = s[j];
    }
    __syncthreads();
    if (threadIdx.x < NSTAT) {
        float t = 0.f;
#pragma unroll
        for (int w = 0; w < BLK_A / 32; w++) t += sm[w][threadIdx.x];
        g_part[blockIdx.x * 72 + threadIdx.x] = t;
    }
}

// ---------------------------------------------------------------------------
// Stage B: PARALLEL reduce of 296x65 partials, then fold BN into A' and e.
// ---------------------------------------------------------------------------
__global__ __launch_bounds__(1024)
void stageB_kernel(const float* __restrict__ W,
                   const float* __restrict__ gamma,
                   const float* __restrict__ beta,
                   int N)
{
    __shared__ float tmp[NSLICE][NSTAT + 1];
    __shared__ float red[NSTAT];
    int slice = threadIdx.x / NSTAT;
    int stat  = threadIdx.x % NSTAT;
    if (slice < NSLICE) {
        float a0 = 0.f, a1 = 0.f, a2 = 0.f, a3 = 0.f;
        int b = slice;
        for (; b + 3 * NSLICE < GRID_A; b += 4 * NSLICE) {
            a0 += g_part[(b + 0 * NSLICE) * 72 + stat];
            a1 += g_part[(b + 1 * NSLICE) * 72 + stat];
            a2 += g_part[(b + 2 * NSLICE) * 72 + stat];
            a3 += g_part[(b + 3 * NSLICE) * 72 + stat];
        }
        for (; b < GRID_A; b += NSLICE) a0 += g_part[b * 72 + stat];
        tmp[slice][stat] = (a0 + a1) + (a2 + a3);
    }
    __syncthreads();
    int t = threadIdx.x;
    if (t < NSTAT) {
        float a = 0.f;
#pragma unroll
        for (int sl = 0; sl < NSLICE; sl++) a += tmp[sl][t];
        red[t] = a;
    }
    __syncthreads();
    if (t < C_MLP) {
        float w[11];
#pragma unroll
        for (int k = 0; k < 11; k++) w[k] = W[k * C_MLP + t];
        float a[NV];
        a[0] = w[0] + w[3];
        a[1] = w[1] + w[4];
        a[2] = w[2] + w[5];
#pragma unroll
        for (int k = 0; k < 5; k++) a[3 + k] = w[6 + k];
        a[8] = -w[0];
        a[9] = -w[1];
        float bb = -CZ * w[2];

        const float invN = 1.0f / (float)N;
        float mva = 0.f;
#pragma unroll
        for (int k = 0; k < NV; k++) mva = fmaf(a[k], red[NPAIR + k] * invN, mva);

        float quad = 0.f;
        int j = 0;
#pragma unroll
        for (int p = 0; p < NV; p++) {
            quad = fmaf(a[p] * a[p], red[j], quad);  j++;
#pragma unroll
            for (int q = p + 1; q < NV; q++) {
                quad = fmaf(2.f * a[p] * a[q], red[j], quad);  j++;
            }
        }
        quad *= invN;

        float mean = mva + bb;
        float ex2  = quad + 2.f * bb * mva + bb * bb;
        float var  = ex2 - mean * mean;
        float sc   = gamma[t] * rsqrtf(var + BN_EPS);

#pragma unroll
        for (int k = 0; k < NV; k++) g_A[k * C_MLP + t] = sc * a[k];
        g_e[t] = beta[t] - sc * mva;
    }
}

// ---------------------------------------------------------------------------
// Pool: WARP = PILLAR, LANE = CHANNEL, fp16 payload. Slots 0..7 (one 128B
// line) are loaded UNCONDITIONALLY and front-batched before cnt/weights/pil
// — payload addresses depend only on p, so the DRAM chain overlaps all other
// loads; stale slots are discarded by the (j < cnt) predicate. 78% of
// pillars finish with zero extra chains; warp-uniform tail loop for cnt>8.
// d = cx*(a0+a8)+cy*(a1+a9)+e post-loop; m init -inf -> empty = 0 via relu.
// Resets g_cnt for the next launch.
// ---------------------------------------------------------------------------
__device__ __forceinline__ float dot8_h(uint4 pk,
                                        float w0, float w1, float w2, float w3,
                                        float w4, float w5, float w6, float w7)
{
    __half2 a, b, c, d;
    memcpy(&a, &pk.x, 4);
    memcpy(&b, &pk.y, 4);
    memcpy(&c, &pk.z, 4);
    memcpy(&d, &pk.w, 4);
    float2 v01 = __half22float2(a);
    float2 v23 = __half22float2(b);
    float2 v45 = __half22float2(c);
    float2 v67 = __half22float2(d);
    float h = v01.x * w0;
    h = fmaf(v01.y, w1, h);
    h = fmaf(v23.x, w2, h);
    h = fmaf(v23.y, w3, h);
    h = fmaf(v45.x, w4, h);
    h = fmaf(v45.y, w5, h);
    h = fmaf(v67.x, w6, h);
    h = fmaf(v67.y, w7, h);
    return h;
}

__global__ __launch_bounds__(256)
void pool_kernel(const int* __restrict__ pil,
                 float* __restrict__ out,
                 int M)
{
    int wid  = threadIdx.x >> 5;
    int lane = threadIdx.x & 31;
    int p    = blockIdx.x * 8 + wid;
    if (p >= M) return;

    // Front-batch: 8 unconditional uniform LDG.128 (slots 0..7 = one 128B line)
    const uint4* pay = g_pay + (size_t)p * CAP;
    uint4 P0 = __ldg(&pay[0]);
    uint4 P1 = __ldg(&pay[1]);
    uint4 P2 = __ldg(&pay[2]);
    uint4 P3 = __ldg(&pay[3]);
    uint4 P4 = __ldg(&pay[4]);
    uint4 P5 = __ldg(&pay[5]);
    uint4 P6 = __ldg(&pay[6]);
    uint4 P7 = __ldg(&pay[7]);

    int cnt = g_cnt[p];
    int px  = __ldg(&pil[3 * p + 2]);
    int py  = __ldg(&pil[3 * p + 1]);

    float w0 = g_A[0 * C_MLP + lane];
    float w1 = g_A[1 * C_MLP + lane];
    float w2 = g_A[2 * C_MLP + lane];
    float w3 = g_A[3 * C_MLP + lane];
    float w4 = g_A[4 * C_MLP + lane];
    float w5 = g_A[5 * C_MLP + lane];
    float w6 = g_A[6 * C_MLP + lane];
    float w7 = g_A[7 * C_MLP + lane];
    float a8 = g_A[8 * C_MLP + lane];
    float a9 = g_A[9 * C_MLP + lane];
    float e  = g_e[lane];

    if (lane == 0) g_cnt[p] = 0;        // reset for next launch
    if (cnt > CAP) cnt = CAP;

    const float NEG_INF = __int_as_float(0xff800000);
    float m = NEG_INF;

    {
        float h0 = dot8_h(P0, w0, w1, w2, w3, w4, w5, w6, w7);
        float h1 = dot8_h(P1, w0, w1, w2, w3, w4, w5, w6, w7);
        float h2 = dot8_h(P2, w0, w1, w2, w3, w4, w5, w6, w7);
        float h3 = dot8_h(P3, w0, w1, w2, w3, w4, w5, w6, w7);
        float h4 = dot8_h(P4, w0, w1, w2, w3, w4, w5, w6, w7);
        float h5 = dot8_h(P5, w0, w1, w2, w3, w4, w5, w6, w7);
        float h6 = dot8_h(P6, w0, w1, w2, w3, w4, w5, w6, w7);
        float h7 = dot8_h(P7, w0, w1, w2, w3, w4, w5, w6, w7);
        m = (0 < cnt) ? fmaxf(m, h0) : m;
        m = (1 < cnt) ? fmaxf(m, h1) : m;
        m = (2 < cnt) ? fmaxf(m, h2) : m;
        m = (3 < cnt) ? fmaxf(m, h3) : m;
        m = (4 < cnt) ? fmaxf(m, h4) : m;
        m = (5 < cnt) ? fmaxf(m, h5) : m;
        m = (6 < cnt) ? fmaxf(m, h6) : m;
        m = (7 < cnt) ? fmaxf(m, h7) : m;
    }

    // warp-uniform rare tail (P(cnt>8) ~ 0.22)
    if (cnt > 8) {
        int j = 8;
        for (; j + 4 <= cnt; j += 4) {
            uint4 Q0 = __ldg(&pay[j + 0]);
            uint4 Q1 = __ldg(&pay[j + 1]);
            uint4 Q2 = __ldg(&pay[j + 2]);
            uint4 Q3 = __ldg(&pay[j + 3]);
            float h0 = dot8_h(Q0, w0, w1, w2, w3, w4, w5, w6, w7);
            float h1 = dot8_h(Q1, w0, w1, w2, w3, w4, w5, w6, w7);
            float h2 = dot8_h(Q2, w0, w1, w2, w3, w4, w5, w6, w7);
            float h3 = dot8_h(Q3, w0, w1, w2, w3, w4, w5, w6, w7);
            m = fmaxf(m, fmaxf(fmaxf(h0, h1), fmaxf(h2, h3)));
        }
        for (; j < cnt; j++) {
            uint4 Q = __ldg(&pay[j]);
            m = fmaxf(m, dot8_h(Q, w0, w1, w2, w3, w4, w5, w6, w7));
        }
    }

    float cx = ((float)px + 0.5f) * PSIZE + XMIN;
    float cy = ((float)py + 0.5f) * PSIZE + YMIN;
    float d  = fmaf(cx, w0 + a8, fmaf(cy, w1 + a9, e));
    out[(size_t)p * C_MLP + lane] = fmaxf(m + d, 0.f);
}

// ---------------------------------------------------------------------------
extern "C" void kernel_launch(void* const* d_in, const int* in_sizes, int n_in,
                              void* d_out, int out_size)
{
    const float* xyz   = (const float*)d_in[0];   // (N,3)
    const float* ptf   = (const float*)d_in[1];   // (N,5)
    const float* W1    = (const float*)d_in[2];   // (11,32)
    const float* gamma = (const float*)d_in[3];   // (32)
    const float* beta  = (const float*)d_in[4];   // (32)
    const int*   pil   = (const int*)d_in[5];     // (M,3)
    const int*   psi   = (const int*)d_in[6];     // (N)
    int N = in_sizes[6];
    int M = in_sizes[5] / 3;
    float* out = (float*)d_out;                   // (M,32)

    scatter_kernel<<<(N + 255) / 256, 256>>>(xyz, ptf, pil, psi, N);
    stats_kernel<<<GRID_A, BLK_A>>>(xyz, ptf, pil, psi, N);
    stageB_kernel<<<1, 1024>>>(W1, gamma, beta, N);
    pool_kernel<<<(M + 7) / 8, 256>>>(pil, out, M);
}

// round 16
// speedup vs baseline: 2.7184x; 2.7184x over previous
#include <cuda_runtime.h>
#include <cuda_fp16.h>

#define C_MLP 32
#define NV    10              // v = (x,y,z,f0..4,cx,cy)
#define NPAIR 55              // upper triangle of 10x10
#define NSTAT 65              // 55 + 10
#define GRID_A 296
#define BLK_A  256
#define NSLICE 15             // stageB reduction slices
#define PSIZE  0.075f
#define XMIN  -54.0f
#define YMIN  -54.0f
#define CZ    -1.0f
#define BN_EPS 1e-3f
#define MMAX   131072
#define CAP    24             // P(cnt>24) ~ 3e-8 for Poisson(6.67)

// static scratch (BSS zero-init; g_cnt kept zeroed by pool_kernel)
__device__ float g_part[GRID_A * 72];        // per-block partial stats
__device__ float g_A[NV * C_MLP];            // folded weights A' (10 x 32)
__device__ float g_e[C_MLP];                 // folded bias
__device__ int   g_cnt[MMAX];
__device__ uint4 g_pay[(size_t)MMAX * CAP];  // fp16 payloads (16B/pt): xc,yc,z,f0..f4

__device__ __forceinline__ unsigned pack_h2(float a, float b) {
    __half2 h = __floats2half2_rn(a, b);
    unsigned u;
    memcpy(&u, &h, 4);
    return u;
}

// ---------------------------------------------------------------------------
// Scatter: compute pillar-relative coords, pack 8 fp16, one STG.128.
// ---------------------------------------------------------------------------
__global__ __launch_bounds__(256)
void scatter_kernel(const float* __restrict__ xyz,
                    const float* __restrict__ ptf,
                    const int*   __restrict__ pil,
                    const int*   __restrict__ psi,
                    int N)
{
    int i = blockIdx.x * blockDim.x + threadIdx.x;
    if (i >= N) return;
    int p  = psi[i];
    int py = pil[3 * p + 1];
    int px = pil[3 * p + 2];
    float cx = ((float)px + 0.5f) * PSIZE + XMIN;
    float cy = ((float)py + 0.5f) * PSIZE + YMIN;
    float x  = xyz[3 * i + 0] - cx;
    float y  = xyz[3 * i + 1] - cy;
    float z  = xyz[3 * i + 2];
    float f0 = ptf[5 * i + 0];
    float f1 = ptf[5 * i + 1];
    float f2 = ptf[5 * i + 2];
    float f3 = ptf[5 * i + 3];
    float f4 = ptf[5 * i + 4];

    uint4 pk;
    pk.x = pack_h2(x,  y);
    pk.y = pack_h2(z,  f0);
    pk.z = pack_h2(f1, f2);
    pk.w = pack_h2(f3, f4);

    int pos = atomicAdd(&g_cnt[p], 1);
    if (pos < CAP) g_pay[(size_t)p * CAP + pos] = pk;
}

// ---------------------------------------------------------------------------
// Stats: sums + second moments of v = (x,y,z,f0..4,cx,cy). (fp32 exact)
// ---------------------------------------------------------------------------
__global__ __launch_bounds__(BLK_A)
void stats_kernel(const float* __restrict__ xyz,
                  const float* __restrict__ ptf,
                  const int*   __restrict__ pil,
                  const int*   __restrict__ psi,
                  int N)
{
    float acc[NPAIR];
    float s[NV];
#pragma unroll
    for (int j = 0; j < NPAIR; j++) acc[j] = 0.f;
#pragma unroll
    for (int j = 0; j < NV; j++) s[j] = 0.f;

    const int stride = GRID_A * BLK_A;
    for (int i = blockIdx.x * BLK_A + threadIdx.x; i < N; i += stride) {
        int p  = psi[i];
        int py = pil[3 * p + 1];
        int px = pil[3 * p + 2];
        float v[NV];
        v[0] = xyz[3 * i + 0];
        v[1] = xyz[3 * i + 1];
        v[2] = xyz[3 * i + 2];
#pragma unroll
        for (int k = 0; k < 5; k++) v[3 + k] = ptf[5 * i + k];
        v[8] = ((float)px + 0.5f) * PSIZE + XMIN;
        v[9] = ((float)py + 0.5f) * PSIZE + YMIN;

        int j = 0;
#pragma unroll
        for (int a = 0; a < NV; a++) {
            s[a] += v[a];
#pragma unroll
            for (int b = a; b < NV; b++) {
                acc[j] = fmaf(v[a], v[b], acc[j]);
                j++;
            }
        }
    }

#pragma unroll
    for (int j = 0; j < NPAIR; j++) {
        float t = acc[j];
        t += __shfl_xor_sync(0xffffffffu, t, 16);
        t += __shfl_xor_sync(0xffffffffu, t, 8);
        t += __shfl_xor_sync(0xffffffffu, t, 4);
        t += __shfl_xor_sync(0xffffffffu, t, 2);
        t += __shfl_xor_sync(0xffffffffu, t, 1);
        acc[j] = t;
    }
#pragma unroll
    for (int j = 0; j < NV; j++) {
        float t = s[j];
        t += __shfl_xor_sync(0xffffffffu, t, 16);
        t += __shfl_xor_sync(0xffffffffu, t, 8);
        t += __shfl_xor_sync(0xffffffffu, t, 4);
        t += __shfl_xor_sync(0xffffffffu, t, 2);
        t += __shfl_xor_sync(0xffffffffu, t, 1);
        s[j] = t;
    }

    __shared__ float sm[BLK_A / 32][NSTAT];
    int lane = threadIdx.x & 31;
    int wid  = threadIdx.x >> 5;
    if (lane == 0) {
#pragma unroll
        for (int j = 0; j < NPAIR; j++) sm[wid][j] = acc[j];
#pragma unroll
        for (int j = 0; j < NV; j++) sm[wid][NPAIR + j] = s[j];
    }
    __syncthreads();
    if (threadIdx.x < NSTAT) {
        float t = 0.f;
#pragma unroll
        for (int w = 0; w < BLK_A / 32; w++) t += sm[w][threadIdx.x];
        g_part[blockIdx.x * 72 + threadIdx.x] = t;
    }
}

// ---------------------------------------------------------------------------
// Stage B: PARALLEL reduce of 296x65 partials, then fold BN into A' and e.
// ---------------------------------------------------------------------------
__global__ __launch_bounds__(1024)
void stageB_kernel(const float* __restrict__ W,
                   const float* __restrict__ gamma,
                   const float* __restrict__ beta,
                   int N)
{
    __shared__ float tmp[NSLICE][NSTAT + 1];
    __shared__ float red[NSTAT];
    int slice = threadIdx.x / NSTAT;
    int stat  = threadIdx.x % NSTAT;
    if (slice < NSLICE) {
        float a0 = 0.f, a1 = 0.f, a2 = 0.f, a3 = 0.f;
        int b = slice;
        for (; b + 3 * NSLICE < GRID_A; b += 4 * NSLICE) {
            a0 += g_part[(b + 0 * NSLICE) * 72 + stat];
            a1 += g_part[(b + 1 * NSLICE) * 72 + stat];
            a2 += g_part[(b + 2 * NSLICE) * 72 + stat];
            a3 += g_part[(b + 3 * NSLICE) * 72 + stat];
        }
        for (; b < GRID_A; b += NSLICE) a0 += g_part[b * 72 + stat];
        tmp[slice][stat] = (a0 + a1) + (a2 + a3);
    }
    __syncthreads();
    int t = threadIdx.x;
    if (t < NSTAT) {
        float a = 0.f;
#pragma unroll
        for (int sl = 0; sl < NSLICE; sl++) a += tmp[sl][t];
        red[t] = a;
    }
    __syncthreads();
    if (t < C_MLP) {
        float w[11];
#pragma unroll
        for (int k = 0; k < 11; k++) w[k] = W[k * C_MLP + t];
        float a[NV];
        a[0] = w[0] + w[3];
        a[1] = w[1] + w[4];
        a[2] = w[2] + w[5];
#pragma unroll
        for (int k = 0; k < 5; k++) a[3 + k] = w[6 + k];
        a[8] = -w[0];
        a[9] = -w[1];
        float bb = -CZ * w[2];

        const float invN = 1.0f / (float)N;
        float mva = 0.f;
#pragma unroll
        for (int k = 0; k < NV; k++) mva = fmaf(a[k], red[NPAIR + k] * invN, mva);

        float quad = 0.f;
        int j = 0;
#pragma unroll
        for (int p = 0; p < NV; p++) {
            quad = fmaf(a[p] * a[p], red[j], quad);  j++;
#pragma unroll
            for (int q = p + 1; q < NV; q++) {
                quad = fmaf(2.f * a[p] * a[q], red[j], quad);  j++;
            }
        }
        quad *= invN;

        float mean = mva + bb;
        float ex2  = quad + 2.f * bb * mva + bb * bb;
        float var  = ex2 - mean * mean;
        float sc   = gamma[t] * rsqrtf(var + BN_EPS);

#pragma unroll
        for (int k = 0; k < NV; k++) g_A[k * C_MLP + t] = sc * a[k];
        g_e[t] = beta[t] - sc * mva;
    }
}

// ---------------------------------------------------------------------------
// Pool: WARP = PILLAR, LANE = CHANNEL, fp16 payload. Slots 0..7 (one 128B
// line) are loaded UNCONDITIONALLY and front-batched. __launch_bounds__(256,3)
// grants ~85 regs/thread so ptxas can hold all 8 uint4 in flight (the R15
// failure was a 42-reg budget serializing these loads). Stale slots are
// discarded by the (j < cnt) predicate. Warp-uniform tail loop for cnt>8.
// d = cx*(a0+a8)+cy*(a1+a9)+e post-loop; m init -inf -> empty = 0 via relu.
// Resets g_cnt for the next launch.
// ---------------------------------------------------------------------------
__device__ __forceinline__ float dot8_h(uint4 pk,
                                        float w0, float w1, float w2, float w3,
                                        float w4, float w5, float w6, float w7)
{
    __half2 a, b, c, d;
    memcpy(&a, &pk.x, 4);
    memcpy(&b, &pk.y, 4);
    memcpy(&c, &pk.z, 4);
    memcpy(&d, &pk.w, 4);
    float2 v01 = __half22float2(a);
    float2 v23 = __half22float2(b);
    float2 v45 = __half22float2(c);
    float2 v67 = __half22float2(d);
    float h = v01.x * w0;
    h = fmaf(v01.y, w1, h);
    h = fmaf(v23.x, w2, h);
    h = fmaf(v23.y, w3, h);
    h = fmaf(v45.x, w4, h);
    h = fmaf(v45.y, w5, h);
    h = fmaf(v67.x, w6, h);
    h = fmaf(v67.y, w7, h);
    return h;
}

__global__ __launch_bounds__(256, 3)
void pool_kernel(const int* __restrict__ pil,
                 float* __restrict__ out,
                 int M)
{
    int wid  = threadIdx.x >> 5;
    int lane = threadIdx.x & 31;
    int p    = blockIdx.x * 8 + wid;
    if (p >= M) return;

    // Front-batch: 8 unconditional uniform LDG.128 (slots 0..7 = one 128B line)
    const uint4* pay = g_pay + (size_t)p * CAP;
    uint4 P0 = __ldg(&pay[0]);
    uint4 P1 = __ldg(&pay[1]);
    uint4 P2 = __ldg(&pay[2]);
    uint4 P3 = __ldg(&pay[3]);
    uint4 P4 = __ldg(&pay[4]);
    uint4 P5 = __ldg(&pay[5]);
    uint4 P6 = __ldg(&pay[6]);
    uint4 P7 = __ldg(&pay[7]);

    int cnt = g_cnt[p];
    int px  = __ldg(&pil[3 * p + 2]);
    int py  = __ldg(&pil[3 * p + 1]);

    float w0 = g_A[0 * C_MLP + lane];
    float w1 = g_A[1 * C_MLP + lane];
    float w2 = g_A[2 * C_MLP + lane];
    float w3 = g_A[3 * C_MLP + lane];
    float w4 = g_A[4 * C_MLP + lane];
    float w5 = g_A[5 * C_MLP + lane];
    float w6 = g_A[6 * C_MLP + lane];
    float w7 = g_A[7 * C_MLP + lane];
    float a8 = g_A[8 * C_MLP + lane];
    float a9 = g_A[9 * C_MLP + lane];
    float e  = g_e[lane];

    if (lane == 0) g_cnt[p] = 0;        // reset for next launch
    if (cnt > CAP) cnt = CAP;

    const float NEG_INF = __int_as_float(0xff800000);
    float m = NEG_INF;

    {
        float h0 = dot8_h(P0, w0, w1, w2, w3, w4, w5, w6, w7);
        float h1 = dot8_h(P1, w0, w1, w2, w3, w4, w5, w6, w7);
        float h2 = dot8_h(P2, w0, w1, w2, w3, w4, w5, w6, w7);
        float h3 = dot8_h(P3, w0, w1, w2, w3, w4, w5, w6, w7);
        float h4 = dot8_h(P4, w0, w1, w2, w3, w4, w5, w6, w7);
        float h5 = dot8_h(P5, w0, w1, w2, w3, w4, w5, w6, w7);
        float h6 = dot8_h(P6, w0, w1, w2, w3, w4, w5, w6, w7);
        float h7 = dot8_h(P7, w0, w1, w2, w3, w4, w5, w6, w7);
        m = (0 < cnt) ? fmaxf(m, h0) : m;
        m = (1 < cnt) ? fmaxf(m, h1) : m;
        m = (2 < cnt) ? fmaxf(m, h2) : m;
        m = (3 < cnt) ? fmaxf(m, h3) : m;
        m = (4 < cnt) ? fmaxf(m, h4) : m;
        m = (5 < cnt) ? fmaxf(m, h5) : m;
        m = (6 < cnt) ? fmaxf(m, h6) : m;
        m = (7 < cnt) ? fmaxf(m, h7) : m;
    }

    // warp-uniform rare tail (P(cnt>8) ~ 0.22)
    if (cnt > 8) {
        int j = 8;
        for (; j + 4 <= cnt; j += 4) {
            uint4 Q0 = __ldg(&pay[j + 0]);
            uint4 Q1 = __ldg(&pay[j + 1]);
            uint4 Q2 = __ldg(&pay[j + 2]);
            uint4 Q3 = __ldg(&pay[j + 3]);
            float h0 = dot8_h(Q0, w0, w1, w2, w3, w4, w5, w6, w7);
            float h1 = dot8_h(Q1, w0, w1, w2, w3, w4, w5, w6, w7);
            float h2 = dot8_h(Q2, w0, w1, w2, w3, w4, w5, w6, w7);
            float h3 = dot8_h(Q3, w0, w1, w2, w3, w4, w5, w6, w7);
            m = fmaxf(m, fmaxf(fmaxf(h0, h1), fmaxf(h2, h3)));
        }
        for (; j < cnt; j++) {
            uint4 Q = __ldg(&pay[j]);
            m = fmaxf(m, dot8_h(Q, w0, w1, w2, w3, w4, w5, w6, w7));
        }
    }

    float cx = ((float)px + 0.5f) * PSIZE + XMIN;
    float cy = ((float)py + 0.5f) * PSIZE + YMIN;
    float d  = fmaf(cx, w0 + a8, fmaf(cy, w1 + a9, e));
    out[(size_t)p * C_MLP + lane] = fmaxf(m + d, 0.f);
}

// ---------------------------------------------------------------------------
extern "C" void kernel_launch(void* const* d_in, const int* in_sizes, int n_in,
                              void* d_out, int out_size)
{
    const float* xyz   = (const float*)d_in[0];   // (N,3)
    const float* ptf   = (const float*)d_in[1];   // (N,5)
    const float* W1    = (const float*)d_in[2];   // (11,32)
    const float* gamma = (const float*)d_in[3];   // (32)
    const float* beta  = (const float*)d_in[4];   // (32)
    const int*   pil   = (const int*)d_in[5];     // (M,3)
    const int*   psi   = (const int*)d_in[6];     // (N)
    int N = in_sizes[6];
    int M = in_sizes[5] / 3;
    float* out = (float*)d_out;                   // (M,32)

    scatter_kernel<<<(N + 255) / 256, 256>>>(xyz, ptf, pil, psi, N);
    stats_kernel<<<GRID_A, BLK_A>>>(xyz, ptf, pil, psi, N);
    stageB_kernel<<<1, 1024>>>(W1, gamma, beta, N);
    pool_kernel<<<(M + 7) / 8, 256>>>(pil, out, M);
}

// round 17
// speedup vs baseline: 2.9648x; 1.0906x over previous
#include <cuda_runtime.h>
#include <cuda_fp16.h>

#define C_MLP 32
#define NV    10              // v = (x,y,z,f0..4,cx,cy)
#define NPAIR 55              // upper triangle of 10x10
#define NSTAT 65              // 55 + 10
#define GRID_A 296
#define BLK_A  256
#define NSLICE 15             // stageB reduction slices
#define PSIZE  0.075f
#define XMIN  -54.0f
#define YMIN  -54.0f
#define CZ    -1.0f
#define BN_EPS 1e-3f
#define MMAX   131072
#define CAP    24             // P(cnt>24) ~ 3e-8 for Poisson(6.67)

// static scratch (BSS zero-init; g_cnt kept zeroed by pool_kernel)
__device__ float g_part[GRID_A * 72];        // per-block partial stats
__device__ float g_A[NV * C_MLP];            // folded weights A' (10 x 32)
__device__ float g_e[C_MLP];                 // folded bias
__device__ int   g_cnt[MMAX];
__device__ uint4 g_pay[(size_t)MMAX * CAP];  // fp16 payloads (16B/pt): xc,yc,z,f0..f4

__device__ __forceinline__ unsigned pack_h2(float a, float b) {
    __half2 h = __floats2half2_rn(a, b);
    unsigned u;
    memcpy(&u, &h, 4);
    return u;
}

// ---------------------------------------------------------------------------
// Fused stats + scatter: ONE pass over all point data. Per point:
//   - gather psi, pil -> cx,cy
//   - accumulate 10-var sums + second moments (fp32 exact, for BN)
//   - pack (x-cx, y-cy, z, f0..f4) as 8 fp16 and scatter into the pillar
//     bucket (one STG.128 + one atomic)
// Saves a full 25.6MB read pass + duplicate psi/pil gathers + one launch
// vs the split scatter/stats pipeline.
// ---------------------------------------------------------------------------
__global__ __launch_bounds__(BLK_A)
void stats_scatter_kernel(const float* __restrict__ xyz,
                          const float* __restrict__ ptf,
                          const int*   __restrict__ pil,
                          const int*   __restrict__ psi,
                          int N)
{
    float acc[NPAIR];
    float s[NV];
#pragma unroll
    for (int j = 0; j < NPAIR; j++) acc[j] = 0.f;
#pragma unroll
    for (int j = 0; j < NV; j++) s[j] = 0.f;

    const int stride = GRID_A * BLK_A;
    for (int i = blockIdx.x * BLK_A + threadIdx.x; i < N; i += stride) {
        int p  = psi[i];
        int py = pil[3 * p + 1];
        int px = pil[3 * p + 2];
        float cx = ((float)px + 0.5f) * PSIZE + XMIN;
        float cy = ((float)py + 0.5f) * PSIZE + YMIN;

        float v[NV];
        v[0] = xyz[3 * i + 0];
        v[1] = xyz[3 * i + 1];
        v[2] = xyz[3 * i + 2];
#pragma unroll
        for (int k = 0; k < 5; k++) v[3 + k] = ptf[5 * i + k];
        v[8] = cx;
        v[9] = cy;

        // scatter fp16 payload (pillar-relative x,y)
        uint4 pk;
        pk.x = pack_h2(v[0] - cx, v[1] - cy);
        pk.y = pack_h2(v[2], v[3]);
        pk.z = pack_h2(v[4], v[5]);
        pk.w = pack_h2(v[6], v[7]);
        int pos = atomicAdd(&g_cnt[p], 1);
        if (pos < CAP) g_pay[(size_t)p * CAP + pos] = pk;

        // stats accumulation
        int j = 0;
#pragma unroll
        for (int a = 0; a < NV; a++) {
            s[a] += v[a];
#pragma unroll
            for (int b = a; b < NV; b++) {
                acc[j] = fmaf(v[a], v[b], acc[j]);
                j++;
            }
        }
    }

#pragma unroll
    for (int j = 0; j < NPAIR; j++) {
        float t = acc[j];
        t += __shfl_xor_sync(0xffffffffu, t, 16);
        t += __shfl_xor_sync(0xffffffffu, t, 8);
        t += __shfl_xor_sync(0xffffffffu, t, 4);
        t += __shfl_xor_sync(0xffffffffu, t, 2);
        t += __shfl_xor_sync(0xffffffffu, t, 1);
        acc[j] = t;
    }
#pragma unroll
    for (int j = 0; j < NV; j++) {
        float t = s[j];
        t += __shfl_xor_sync(0xffffffffu, t, 16);
        t += __shfl_xor_sync(0xffffffffu, t, 8);
        t += __shfl_xor_sync(0xffffffffu, t, 4);
        t += __shfl_xor_sync(0xffffffffu, t, 2);
        t += __shfl_xor_sync(0xffffffffu, t, 1);
        s[j] = t;
    }

    __shared__ float sm[BLK_A / 32][NSTAT];
    int lane = threadIdx.x & 31;
    int wid  = threadIdx.x >> 5;
    if (lane == 0) {
#pragma unroll
        for (int j = 0; j < NPAIR; j++) sm[wid][j] = acc[j];
#pragma unroll
        for (int j = 0; j < NV; j++) sm[wid][NPAIR + j] = s[j];
    }
    __syncthreads();
    if (threadIdx.x < NSTAT) {
        float t = 0.f;
#pragma unroll
        for (int w = 0; w < BLK_A / 32; w++) t += sm[w][threadIdx.x];
        g_part[blockIdx.x * 72 + threadIdx.x] = t;
    }
}

// ---------------------------------------------------------------------------
// Stage B: PARALLEL reduce of 296x65 partials, then fold BN into A' and e.
// ---------------------------------------------------------------------------
__global__ __launch_bounds__(1024)
void stageB_kernel(const float* __restrict__ W,
                   const float* __restrict__ gamma,
                   const float* __restrict__ beta,
                   int N)
{
    __shared__ float tmp[NSLICE][NSTAT + 1];
    __shared__ float red[NSTAT];
    int slice = threadIdx.x / NSTAT;
    int stat  = threadIdx.x % NSTAT;
    if (slice < NSLICE) {
        float a0 = 0.f, a1 = 0.f, a2 = 0.f, a3 = 0.f;
        int b = slice;
        for (; b + 3 * NSLICE < GRID_A; b += 4 * NSLICE) {
            a0 += g_part[(b + 0 * NSLICE) * 72 + stat];
            a1 += g_part[(b + 1 * NSLICE) * 72 + stat];
            a2 += g_part[(b + 2 * NSLICE) * 72 + stat];
            a3 += g_part[(b + 3 * NSLICE) * 72 + stat];
        }
        for (; b < GRID_A; b += NSLICE) a0 += g_part[b * 72 + stat];
        tmp[slice][stat] = (a0 + a1) + (a2 + a3);
    }
    __syncthreads();
    int t = threadIdx.x;
    if (t < NSTAT) {
        float a = 0.f;
#pragma unroll
        for (int sl = 0; sl < NSLICE; sl++) a += tmp[sl][t];
        red[t] = a;
    }
    __syncthreads();
    if (t < C_MLP) {
        float w[11];
#pragma unroll
        for (int k = 0; k < 11; k++) w[k] = W[k * C_MLP + t];
        float a[NV];
        a[0] = w[0] + w[3];
        a[1] = w[1] + w[4];
        a[2] = w[2] + w[5];
#pragma unroll
        for (int k = 0; k < 5; k++) a[3 + k] = w[6 + k];
        a[8] = -w[0];
        a[9] = -w[1];
        float bb = -CZ * w[2];

        const float invN = 1.0f / (float)N;
        float mva = 0.f;
#pragma unroll
        for (int k = 0; k < NV; k++) mva = fmaf(a[k], red[NPAIR + k] * invN, mva);

        float quad = 0.f;
        int j = 0;
#pragma unroll
        for (int p = 0; p < NV; p++) {
            quad = fmaf(a[p] * a[p], red[j], quad);  j++;
#pragma unroll
            for (int q = p + 1; q < NV; q++) {
                quad = fmaf(2.f * a[p] * a[q], red[j], quad);  j++;
            }
        }
        quad *= invN;

        float mean = mva + bb;
        float ex2  = quad + 2.f * bb * mva + bb * bb;
        float var  = ex2 - mean * mean;
        float sc   = gamma[t] * rsqrtf(var + BN_EPS);

#pragma unroll
        for (int k = 0; k < NV; k++) g_A[k * C_MLP + t] = sc * a[k];
        g_e[t] = beta[t] - sc * mva;
    }
}

// ---------------------------------------------------------------------------
// Pool (UNCHANGED from R16 win): WARP = PILLAR, LANE = CHANNEL, fp16
// payload, 8 unconditional front-batched uniform LDG.128 (one 128B line),
// __launch_bounds__(256,3) for the register budget that keeps them in
// flight, predicated max, warp-uniform tail for cnt>8. Resets g_cnt.
// ---------------------------------------------------------------------------
__device__ __forceinline__ float dot8_h(uint4 pk,
                                        float w0, float w1, float w2, float w3,
                                        float w4, float w5, float w6, float w7)
{
    __half2 a, b, c, d;
    memcpy(&a, &pk.x, 4);
    memcpy(&b, &pk.y, 4);
    memcpy(&c, &pk.z, 4);
    memcpy(&d, &pk.w, 4);
    float2 v01 = __half22float2(a);
    float2 v23 = __half22float2(b);
    float2 v45 = __half22float2(c);
    float2 v67 = __half22float2(d);
    float h = v01.x * w0;
    h = fmaf(v01.y, w1, h);
    h = fmaf(v23.x, w2, h);
    h = fmaf(v23.y, w3, h);
    h = fmaf(v45.x, w4, h);
    h = fmaf(v45.y, w5, h);
    h = fmaf(v67.x, w6, h);
    h = fmaf(v67.y, w7, h);
    return h;
}

__global__ __launch_bounds__(256, 3)
void pool_kernel(const int* __restrict__ pil,
                 float* __restrict__ out,
                 int M)
{
    int wid  = threadIdx.x >> 5;
    int lane = threadIdx.x & 31;
    int p    = blockIdx.x * 8 + wid;
    if (p >= M) return;

    const uint4* pay = g_pay + (size_t)p * CAP;
    uint4 P0 = __ldg(&pay[0]);
    uint4 P1 = __ldg(&pay[1]);
    uint4 P2 = __ldg(&pay[2]);
    uint4 P3 = __ldg(&pay[3]);
    uint4 P4 = __ldg(&pay[4]);
    uint4 P5 = __ldg(&pay[5]);
    uint4 P6 = __ldg(&pay[6]);
    uint4 P7 = __ldg(&pay[7]);

    int cnt = g_cnt[p];
    int px  = __ldg(&pil[3 * p + 2]);
    int py  = __ldg(&pil[3 * p + 1]);

    float w0 = g_A[0 * C_MLP + lane];
    float w1 = g_A[1 * C_MLP + lane];
    float w2 = g_A[2 * C_MLP + lane];
    float w3 = g_A[3 * C_MLP + lane];
    float w4 = g_A[4 * C_MLP + lane];
    float w5 = g_A[5 * C_MLP + lane];
    float w6 = g_A[6 * C_MLP + lane];
    float w7 = g_A[7 * C_MLP + lane];
    float a8 = g_A[8 * C_MLP + lane];
    float a9 = g_A[9 * C_MLP + lane];
    float e  = g_e[lane];

    if (lane == 0) g_cnt[p] = 0;        // reset for next launch
    if (cnt > CAP) cnt = CAP;

    const float NEG_INF = __int_as_float(0xff800000);
    float m = NEG_INF;

    {
        float h0 = dot8_h(P0, w0, w1, w2, w3, w4, w5, w6, w7);
        float h1 = dot8_h(P1, w0, w1, w2, w3, w4, w5, w6, w7);
        float h2 = dot8_h(P2, w0, w1, w2, w3, w4, w5, w6, w7);
        float h3 = dot8_h(P3, w0, w1, w2, w3, w4, w5, w6, w7);
        float h4 = dot8_h(P4, w0, w1, w2, w3, w4, w5, w6, w7);
        float h5 = dot8_h(P5, w0, w1, w2, w3, w4, w5, w6, w7);
        float h6 = dot8_h(P6, w0, w1, w2, w3, w4, w5, w6, w7);
        float h7 = dot8_h(P7, w0, w1, w2, w3, w4, w5, w6, w7);
        m = (0 < cnt) ? fmaxf(m, h0) : m;
        m = (1 < cnt) ? fmaxf(m, h1) : m;
        m = (2 < cnt) ? fmaxf(m, h2) : m;
        m = (3 < cnt) ? fmaxf(m, h3) : m;
        m = (4 < cnt) ? fmaxf(m, h4) : m;
        m = (5 < cnt) ? fmaxf(m, h5) : m;
        m = (6 < cnt) ? fmaxf(m, h6) : m;
        m = (7 < cnt) ? fmaxf(m, h7) : m;
    }

    if (cnt > 8) {
        int j = 8;
        for (; j + 4 <= cnt; j += 4) {
            uint4 Q0 = __ldg(&pay[j + 0]);
            uint4 Q1 = __ldg(&pay[j + 1]);
            uint4 Q2 = __ldg(&pay[j + 2]);
            uint4 Q3 = __ldg(&pay[j + 3]);
            float h0 = dot8_h(Q0, w0, w1, w2, w3, w4, w5, w6, w7);
            float h1 = dot8_h(Q1, w0, w1, w2, w3, w4, w5, w6, w7);
            float h2 = dot8_h(Q2, w0, w1, w2, w3, w4, w5, w6, w7);
            float h3 = dot8_h(Q3, w0, w1, w2, w3, w4, w5, w6, w7);
            m = fmaxf(m, fmaxf(fmaxf(h0, h1), fmaxf(h2, h3)));
        }
        for (; j < cnt; j++) {
            uint4 Q = __ldg(&pay[j]);
            m = fmaxf(m, dot8_h(Q, w0, w1, w2, w3, w4, w5, w6, w7));
        }
    }

    float cx = ((float)px + 0.5f) * PSIZE + XMIN;
    float cy = ((float)py + 0.5f) * PSIZE + YMIN;
    float d  = fmaf(cx, w0 + a8, fmaf(cy, w1 + a9, e));
    out[(size_t)p * C_MLP + lane] = fmaxf(m + d, 0.f);
}

// ---------------------------------------------------------------------------
extern "C" void kernel_launch(void* const* d_in, const int* in_sizes, int n_in,
                              void* d_out, int out_size)
{
    const float* xyz   = (const float*)d_in[0];   // (N,3)
    const float* ptf   = (const float*)d_in[1];   // (N,5)
    const float* W1    = (const float*)d_in[2];   // (11,32)
    const float* gamma = (const float*)d_in[3];   // (32)
    const float* beta  = (const float*)d_in[4];   // (32)
    const int*   pil   = (const int*)d_in[5];     // (M,3)
    const int*   psi   = (const int*)d_in[6];     // (N)
    int N = in_sizes[6];
    int M = in_sizes[5] / 3;
    float* out = (float*)d_out;                   // (M,32)

    stats_scatter_kernel<<<GRID_A, BLK_A>>>(xyz, ptf, pil, psi, N);
    stageB_kernel<<<1, 1024>>>(W1, gamma, beta, N);
    pool_kernel<<<(M + 7) / 8, 256>>>(pil, out, M);
}